// round 1
// baseline (speedup 1.0000x reference)
#include <cuda_runtime.h>
#include <cstddef>

#define C_DIM 64
#define H_DIM 150000
#define K_DIM 27

// Scratch: node-major x (x_t[h][c]) and k-major neigh (nt[k][h]).
// __device__ globals — no dynamic allocation (harness rule).
__device__ float g_xt[(size_t)H_DIM * C_DIM];   // 38.4 MB
__device__ int   g_nt[(size_t)K_DIM * H_DIM];   // 16.2 MB

// ---------------------------------------------------------------------------
// Transpose x: (C, H) -> (H, C), tiled 32x32 via shared memory.
// Read coalesced along h, write coalesced along c.
// ---------------------------------------------------------------------------
__global__ void transpose_x_kernel(const float* __restrict__ x) {
    __shared__ float tile[32][33];
    const int hb = blockIdx.x * 32;
    const int cb = blockIdx.y * 32;
    const int tx = threadIdx.x, ty = threadIdx.y;

    const int h_in = hb + tx;
    const int c_in = cb + ty;
    if (h_in < H_DIM)
        tile[ty][tx] = x[(size_t)c_in * H_DIM + h_in];
    __syncthreads();

    const int h_out = hb + ty;
    const int c_out = cb + tx;
    if (h_out < H_DIM)
        g_xt[(size_t)h_out * C_DIM + c_out] = tile[tx][ty];
}

// ---------------------------------------------------------------------------
// Transpose neigh: (H, K) -> (K, H), tiled 32x32 (K=27 < 32, single k-tile).
// ---------------------------------------------------------------------------
__global__ void transpose_n_kernel(const int* __restrict__ nb) {
    __shared__ int tile[32][33];
    const int hb = blockIdx.x * 32;
    const int tx = threadIdx.x, ty = threadIdx.y;

    const int h_in = hb + ty;
    if (h_in < H_DIM && tx < K_DIM)
        tile[ty][tx] = nb[(size_t)h_in * K_DIM + tx];
    __syncthreads();

    const int h_out = hb + tx;
    if (h_out < H_DIM && ty < K_DIM)
        g_nt[(size_t)ty * H_DIM + h_out] = tile[tx][ty];
}

// ---------------------------------------------------------------------------
// Gather: out[c, k, h] = mask ? x_t[n[h,k]][c] : 0
// One thread handles 4 consecutive h for one k. Per 4-channel step:
//   4x LDG.128 (contiguous within a node row, L2-resident),
//   register transpose, 4x STG.128 (coalesced along h).
// ---------------------------------------------------------------------------
__global__ __launch_bounds__(256) void gather_kernel(float* __restrict__ out) {
    const int h4 = blockIdx.x * blockDim.x + threadIdx.x;
    if (h4 >= H_DIM / 4) return;
    const int k = blockIdx.y;
    const int h = h4 * 4;

    // coalesced int4 index load
    const int4 n = *reinterpret_cast<const int4*>(&g_nt[(size_t)k * H_DIM + h]);
    const bool m0 = n.x >= 0, m1 = n.y >= 0, m2 = n.z >= 0, m3 = n.w >= 0;

    const float4* __restrict__ r0 =
        reinterpret_cast<const float4*>(g_xt + (size_t)(m0 ? n.x : 0) * C_DIM);
    const float4* __restrict__ r1 =
        reinterpret_cast<const float4*>(g_xt + (size_t)(m1 ? n.y : 0) * C_DIM);
    const float4* __restrict__ r2 =
        reinterpret_cast<const float4*>(g_xt + (size_t)(m2 ? n.z : 0) * C_DIM);
    const float4* __restrict__ r3 =
        reinterpret_cast<const float4*>(g_xt + (size_t)(m3 ? n.w : 0) * C_DIM);

    const float4 z = make_float4(0.f, 0.f, 0.f, 0.f);
    const size_t KH = (size_t)K_DIM * H_DIM;
    float* __restrict__ p = out + (size_t)k * H_DIM + h;  // channel 0 slot

    #pragma unroll 4
    for (int c4 = 0; c4 < C_DIM / 4; ++c4) {
        const float4 a0 = m0 ? r0[c4] : z;
        const float4 a1 = m1 ? r1[c4] : z;
        const float4 a2 = m2 ? r2[c4] : z;
        const float4 a3 = m3 ? r3[c4] : z;

        *reinterpret_cast<float4*>(p)          = make_float4(a0.x, a1.x, a2.x, a3.x);
        *reinterpret_cast<float4*>(p + KH)     = make_float4(a0.y, a1.y, a2.y, a3.y);
        *reinterpret_cast<float4*>(p + 2 * KH) = make_float4(a0.z, a1.z, a2.z, a3.z);
        *reinterpret_cast<float4*>(p + 3 * KH) = make_float4(a0.w, a1.w, a2.w, a3.w);
        p += 4 * KH;
    }
}

extern "C" void kernel_launch(void* const* d_in, const int* in_sizes, int n_in,
                              void* d_out, int out_size) {
    const float* x  = (const float*)d_in[0];   // (1, 64, 150000, 1) fp32
    const int*   nb = (const int*)d_in[1];     // (150000, 27) int32
    float*       out = (float*)d_out;          // (1, 64, 27, 150000) fp32

    (void)in_sizes; (void)n_in; (void)out_size;

    {
        dim3 block(32, 32);
        dim3 grid((H_DIM + 31) / 32, C_DIM / 32);
        transpose_x_kernel<<<grid, block>>>(x);
    }
    {
        dim3 block(32, 32);
        dim3 grid((H_DIM + 31) / 32, 1);
        transpose_n_kernel<<<grid, block>>>(nb);
    }
    {
        dim3 block(256);
        dim3 grid((H_DIM / 4 + 255) / 256, K_DIM);
        gather_kernel<<<grid, block>>>(out);
    }
}

// round 2
// speedup vs baseline: 1.3151x; 1.3151x over previous
#include <cuda_runtime.h>
#include <cstddef>

#define C_DIM 64
#define H_DIM 150000
#define K_DIM 27
#define H4_DIM (H_DIM / 4)

// Scratch: node-major x (x_t[h][c]) and k-major neigh (nt[k][h]).
__device__ float g_xt[(size_t)H_DIM * C_DIM];   // 38.4 MB
__device__ int   g_nt[(size_t)K_DIM * H_DIM];   // 16.2 MB

// ---------------------------------------------------------------------------
// Transpose x: (C, H) -> (H, C). 32h x 32c tile, block (32,8).
// Loads coalesced along h (4 per thread), writes float4 along c.
// Smem read pattern (4cg + i + row) is bank-conflict-free.
// ---------------------------------------------------------------------------
__global__ __launch_bounds__(256) void transpose_x_kernel(const float* __restrict__ x) {
    __shared__ float tile[32][33];
    const int hb = blockIdx.x * 32;
    const int cb = blockIdx.y * 32;
    const int tx = threadIdx.x, ty = threadIdx.y;

    const int h = hb + tx;
    if (h < H_DIM) {
        #pragma unroll
        for (int i = 0; i < 4; ++i) {
            const int c = cb + ty * 4 + i;
            tile[ty * 4 + i][tx] = x[(size_t)c * H_DIM + h];
        }
    }
    __syncthreads();

    const int j   = ty * 32 + tx;
    const int row = j / 8;      // 0..31 (h within tile)
    const int cg  = j % 8;      // 0..7  (group of 4 channels)
    const int hh  = hb + row;
    if (hh < H_DIM) {
        float4 v = make_float4(tile[cg * 4 + 0][row], tile[cg * 4 + 1][row],
                               tile[cg * 4 + 2][row], tile[cg * 4 + 3][row]);
        *reinterpret_cast<float4*>(&g_xt[(size_t)hh * C_DIM + cb + cg * 4]) = v;
    }
}

// ---------------------------------------------------------------------------
// Transpose neigh: (H, K) -> (K, H), tiled 32x32 (K=27 < 32).
// ---------------------------------------------------------------------------
__global__ void transpose_n_kernel(const int* __restrict__ nb) {
    __shared__ int tile[32][33];
    const int hb = blockIdx.x * 32;
    const int tx = threadIdx.x, ty = threadIdx.y;

    const int h_in = hb + ty;
    if (h_in < H_DIM && tx < K_DIM)
        tile[ty][tx] = nb[(size_t)h_in * K_DIM + tx];
    __syncthreads();

    const int h_out = hb + tx;
    if (h_out < H_DIM && ty < K_DIM)
        g_nt[(size_t)ty * H_DIM + h_out] = tile[tx][ty];
}

// ---------------------------------------------------------------------------
// Gather: out[c, k, h] = mask ? x_t[n[k,h]][c] : 0
// Thread = (4 consecutive h) x (16 channels, selected by blockIdx.z).
// 16 independent LDG.128 batched for MLP, then 16 STG.128 (__stcs so the
// write-once output stream doesn't evict x_t from L2).
// ---------------------------------------------------------------------------
__global__ __launch_bounds__(256) void gather_kernel(float* __restrict__ out) {
    const int h4 = blockIdx.x * blockDim.x + threadIdx.x;
    if (h4 >= H4_DIM) return;
    const int k  = blockIdx.y;
    const int cq = blockIdx.z;          // channel quarter: 16 channels
    const int h  = h4 * 4;

    const int4 n = *reinterpret_cast<const int4*>(&g_nt[(size_t)k * H_DIM + h]);
    const bool m0 = n.x >= 0, m1 = n.y >= 0, m2 = n.z >= 0, m3 = n.w >= 0;

    const int c0 = cq * 16;
    const float4* __restrict__ r0 =
        reinterpret_cast<const float4*>(g_xt + (size_t)(m0 ? n.x : 0) * C_DIM + c0);
    const float4* __restrict__ r1 =
        reinterpret_cast<const float4*>(g_xt + (size_t)(m1 ? n.y : 0) * C_DIM + c0);
    const float4* __restrict__ r2 =
        reinterpret_cast<const float4*>(g_xt + (size_t)(m2 ? n.z : 0) * C_DIM + c0);
    const float4* __restrict__ r3 =
        reinterpret_cast<const float4*>(g_xt + (size_t)(m3 ? n.w : 0) * C_DIM + c0);

    const float4 z = make_float4(0.f, 0.f, 0.f, 0.f);
    float4 a0[4], a1[4], a2[4], a3[4];

    #pragma unroll
    for (int c4 = 0; c4 < 4; ++c4) {
        a0[c4] = m0 ? r0[c4] : z;
        a1[c4] = m1 ? r1[c4] : z;
        a2[c4] = m2 ? r2[c4] : z;
        a3[c4] = m3 ? r3[c4] : z;
    }

    const size_t KH = (size_t)K_DIM * H_DIM;
    float* __restrict__ p = out + (size_t)c0 * KH + (size_t)k * H_DIM + h;

    #pragma unroll
    for (int c4 = 0; c4 < 4; ++c4) {
        __stcs(reinterpret_cast<float4*>(p),          make_float4(a0[c4].x, a1[c4].x, a2[c4].x, a3[c4].x));
        __stcs(reinterpret_cast<float4*>(p + KH),     make_float4(a0[c4].y, a1[c4].y, a2[c4].y, a3[c4].y));
        __stcs(reinterpret_cast<float4*>(p + 2 * KH), make_float4(a0[c4].z, a1[c4].z, a2[c4].z, a3[c4].z));
        __stcs(reinterpret_cast<float4*>(p + 3 * KH), make_float4(a0[c4].w, a1[c4].w, a2[c4].w, a3[c4].w));
        p += 4 * KH;
    }
}

extern "C" void kernel_launch(void* const* d_in, const int* in_sizes, int n_in,
                              void* d_out, int out_size) {
    const float* x   = (const float*)d_in[0];   // (1, 64, 150000, 1) fp32
    const int*   nb  = (const int*)d_in[1];     // (150000, 27) int32
    float*       out = (float*)d_out;           // (1, 64, 27, 150000) fp32

    (void)in_sizes; (void)n_in; (void)out_size;

    {
        dim3 block(32, 8);
        dim3 grid((H_DIM + 31) / 32, C_DIM / 32);
        transpose_x_kernel<<<grid, block>>>(x);
    }
    {
        dim3 block(32, 32);
        dim3 grid((H_DIM + 31) / 32, 1);
        transpose_n_kernel<<<grid, block>>>(nb);
    }
    {
        dim3 block(256);
        dim3 grid((H4_DIM + 255) / 256, K_DIM, 4);
        gather_kernel<<<grid, block>>>(out);
    }
}